// round 15
// baseline (speedup 1.0000x reference)
#include <cuda_runtime.h>
#include <cuda_fp16.h>
#include <cstdint>

#define BATCH 2
#define TQ    2048
#define HID   1280
#define NH    20
#define HD    64
#define CROSSD 2048
#define SENC  77
#define SPAD  128
#define FFD   5120
#define M1    (BATCH*TQ)     /* 4096 */
#define MENC  (BATCH*SENC)   /* 154  */
#define NBH   (BATCH*NH)     /* 40   */

typedef __half h16;

// ---------------- scratch (device globals; no allocation) ----------------
__device__ h16   g_h    [M1*HID];
__device__ h16   g_pqkv [(size_t)M1*3*HID];
__device__ h16   g_pq   [M1*HID];
__device__ h16   g_pkv  [MENC*2*HID];
__device__ h16   g_qh   [(size_t)NBH*TQ*HD];
__device__ h16   g_kh   [(size_t)NBH*TQ*HD];
__device__ h16   g_vT   [(size_t)NBH*HD*TQ];
__device__ h16   g_att  [M1*HID];
__device__ float g_x    [M1*HID];
__device__ h16   g_ff   [(size_t)M1*FFD];
__device__ h16   g_enc  [MENC*CROSSD];
// fp16 weights
__device__ h16   g_wqkv1h[3*HID*HID];
__device__ h16   g_wo1h[HID*HID];
__device__ h16   g_wq2h[HID*HID];
__device__ h16   g_wkv2h[2*HID*CROSSD];
__device__ h16   g_wo2h[HID*HID];
__device__ h16   g_wggh[2*FFD*HID];    // permuted: row 2c = orig c, row 2c+1 = orig FFD+c
__device__ float g_bggp[2*FFD];        // permuted bias
__device__ h16   g_wffh[HID*FFD];

// ---------------- elementwise kernels ----------------
__global__ void f2h_kernel(const float* __restrict__ in, h16* __restrict__ out, long long n) {
    long long i = (long long)blockIdx.x * blockDim.x + threadIdx.x;
    if (i < n) out[i] = __float2half(in[i]);
}

__global__ void permute_wgg_kernel(const float* __restrict__ in, h16* __restrict__ out) {
    long long i = (long long)blockIdx.x * blockDim.x + threadIdx.x;
    if (i >= (long long)2 * FFD * HID) return;
    int k = (int)(i % HID);
    int r = (int)(i / HID);
    int c = r >> 1;
    int srcRow = (r & 1) ? (FFD + c) : c;
    out[i] = __float2half(in[(long long)srcRow * HID + k]);
}

__global__ void permute_bgg_kernel(const float* __restrict__ in, float* __restrict__ out) {
    int i = blockIdx.x * blockDim.x + threadIdx.x;
    if (i >= 2 * FFD) return;
    int c = i >> 1;
    out[i] = in[(i & 1) ? (FFD + c) : c];
}

__global__ void ln_kernel(const float* __restrict__ x, const float* __restrict__ g,
                          const float* __restrict__ b, h16* __restrict__ out) {
    __shared__ float red[256];
    int row = blockIdx.x, tid = threadIdx.x;
    const float* xr = x + (long long)row * HID;
    float v[5], s = 0.f;
#pragma unroll
    for (int i = 0; i < 5; i++) { v[i] = xr[tid + i * 256]; s += v[i]; }
    red[tid] = s; __syncthreads();
    for (int o = 128; o > 0; o >>= 1) { if (tid < o) red[tid] += red[tid + o]; __syncthreads(); }
    float mu = red[0] * (1.0f / HID);
    __syncthreads();
    float sq = 0.f;
#pragma unroll
    for (int i = 0; i < 5; i++) { float d = v[i] - mu; sq += d * d; }
    red[tid] = sq; __syncthreads();
    for (int o = 128; o > 0; o >>= 1) { if (tid < o) red[tid] += red[tid + o]; __syncthreads(); }
    float rs = rsqrtf(red[0] * (1.0f / HID) + 1e-5f);
#pragma unroll
    for (int i = 0; i < 5; i++) {
        int c = tid + i * 256;
        out[(long long)row * HID + c] = __float2half((v[i] - mu) * rs * g[c] + b[c]);
    }
}

__global__ void reshape_q_kernel(const h16* __restrict__ q, h16* __restrict__ qh,
                                 int stride, int colOff) {
    long long idx = (long long)blockIdx.x * blockDim.x + threadIdx.x;
    if (idx >= (long long)NBH * TQ * HD) return;
    int d = idx & (HD - 1);
    long long r = idx >> 6;
    int t = (int)(r % TQ);
    long long bh = r / TQ;
    int h = (int)(bh % NH), b = (int)(bh / NH);
    float v = __half2float(q[((long long)(b * TQ + t)) * stride + colOff + h * HD + d]);
    qh[idx] = __float2half(v * 0.125f);
}

__global__ void reshape_k_kernel(const h16* __restrict__ k, h16* __restrict__ kh,
                                 int S, int Spad, int stride, int colOff) {
    long long idx = (long long)blockIdx.x * blockDim.x + threadIdx.x;
    long long tot = (long long)NBH * Spad * HD;
    if (idx >= tot) return;
    int d = idx & (HD - 1);
    long long r = idx >> 6;
    int s = (int)(r % Spad);
    long long bh = r / Spad;
    int h = (int)(bh % NH), b = (int)(bh / NH);
    h16 val = __float2half(0.f);
    if (s < S) val = k[((long long)(b * S + s)) * stride + colOff + h * HD + d];
    kh[idx] = val;
}

__global__ void reshape_vT_kernel(const h16* __restrict__ v, h16* __restrict__ vT,
                                  int S, int Spad, int stride, int colOff) {
    long long idx = (long long)blockIdx.x * blockDim.x + threadIdx.x;
    long long tot = (long long)NBH * HD * Spad;
    if (idx >= tot) return;
    int s = (int)(idx % Spad);
    long long r = idx / Spad;
    int d = (int)(r % HD);
    long long bh = r / HD;
    int h = (int)(bh % NH), b = (int)(bh / NH);
    h16 val = __float2half(0.f);
    if (s < S) val = v[((long long)(b * S + s)) * stride + colOff + h * HD + d];
    vT[idx] = val;
}

// ---------------- common asm helpers ----------------
__device__ __forceinline__ void mma16816(float c[4], const uint32_t a[4], const uint32_t b[2]) {
    asm volatile(
        "mma.sync.aligned.m16n8k16.row.col.f32.f16.f16.f32 "
        "{%0,%1,%2,%3}, {%4,%5,%6,%7}, {%8,%9}, {%0,%1,%2,%3};\n"
        : "+f"(c[0]), "+f"(c[1]), "+f"(c[2]), "+f"(c[3])
        : "r"(a[0]), "r"(a[1]), "r"(a[2]), "r"(a[3]), "r"(b[0]), "r"(b[1]));
}
__device__ __forceinline__ void cpasync16(uint32_t dst, const void* src, bool pred) {
    int sz = pred ? 16 : 0;
    asm volatile("cp.async.cg.shared.global [%0], [%1], 16, %2;\n"
                 :: "r"(dst), "l"(src), "r"(sz));
}
__device__ __forceinline__ void cp_commit() {
    asm volatile("cp.async.commit_group;\n" ::: "memory");
}
__device__ __forceinline__ void cp_wait0() { asm volatile("cp.async.wait_group 0;\n" ::: "memory"); }
__device__ __forceinline__ void cp_wait1() { asm volatile("cp.async.wait_group 1;\n" ::: "memory"); }
__device__ __forceinline__ uint32_t pack_h2(float a, float b) {
    __half2 v = __floats2half2_rn(a, b);
    return *reinterpret_cast<uint32_t*>(&v);
}

// ---------------- cp.async pipelined batched fp16 GEMM ----------------
// CTA 128x128x64, 128 threads (4 warps 2x2), warp tile 64x64 (128 acc regs):
// 128 B smem fragment traffic per MMA (2x better than 32x32 warp tile).
// 3-stage cp.async (96 KB smem -> 2 CTAs/SM).
// gmode 0: C = scale*(A@W^T)+bias+residual; gmode 1: geglu epilogue.
#define KTILE    64
#define LDS_S    88
#define STG_ELE  (128 * LDS_S)
#define STAGES   3
#define SMEM_BYTES (2 * STAGES * STG_ELE * 2)   /* 135168? no: 2*3*11264*2 = 135168 */

__global__ __launch_bounds__(128, 2) void gemm_kernel(
    const h16* __restrict__ A, const h16* __restrict__ W,
    const float* __restrict__ bias, const float* __restrict__ residual,
    float* __restrict__ Cf, h16* __restrict__ Ch,
    int M, int N, int K,
    long long aStride, long long wStride,
    long long cHi, long long cLo, int cDiv, int ldc, float scale, int gmode)
{
    extern __shared__ __align__(16) h16 sm[];
    h16* sA = sm;
    h16* sB = sm + STAGES * STG_ELE;

    int z = blockIdx.z;
    A += (long long)z * aStride;
    W += (long long)z * wStride;
    long long cOff = (long long)(z / cDiv) * cHi + (long long)(z % cDiv) * cLo;

    int tid = threadIdx.x;
    int lane = tid & 31, warp = tid >> 5;
    int l4 = lane & 3, ln4 = lane >> 2;
    int wm = warp >> 1, wn = warp & 1;        // 2x2 warp grid, 64x64 warp tile
    int rowBase = blockIdx.y * 128;
    int colBase = blockIdx.x * 128;

    uint32_t sA_u = (uint32_t)__cvta_generic_to_shared(sA);
    uint32_t sB_u = (uint32_t)__cvta_generic_to_shared(sB);

    // copy mapping: 8 chunks of 16B per operand per thread per k-tile
    int cr[8], cc[8];
#pragma unroll
    for (int jt = 0; jt < 8; ++jt) {
        int j = tid + jt * 128;
        cr[jt] = j >> 3;
        cc[jt] = (j & 7) << 3;
    }

    float acc[4][8][4];
#pragma unroll
    for (int i = 0; i < 4; i++)
#pragma unroll
        for (int j = 0; j < 8; j++)
#pragma unroll
            for (int l = 0; l < 4; l++) acc[i][j][l] = 0.f;

    int kTiles = K >> 6;

    auto issue = [&](int st, int k0) {
        uint32_t aBase = sA_u + st * (STG_ELE * 2);
        uint32_t bBase = sB_u + st * (STG_ELE * 2);
#pragma unroll
        for (int jt = 0; jt < 8; ++jt) {
            int r = cr[jt], c = cc[jt];
            uint32_t soff = (uint32_t)(r * LDS_S + c) * 2;
            int gr = rowBase + r;
            int grc = gr < M ? gr : (M - 1);
            cpasync16(aBase + soff, A + (long long)grc * K + k0 + c, gr < M);
            int gn = colBase + r;
            int gnc = gn < N ? gn : (N - 1);
            cpasync16(bBase + soff, W + (long long)gnc * K + k0 + c, gn < N);
        }
    };

    // prologue: 2 stages in flight
#pragma unroll
    for (int f = 0; f < STAGES - 1; ++f) {
        if (f < kTiles) issue(f, f << 6);
        cp_commit();
    }

    for (int kt = 0; kt < kTiles; ++kt) {
        cp_wait1();
        __syncthreads();
        int nf = kt + STAGES - 1;
        if (nf < kTiles) issue(nf % STAGES, nf << 6);
        cp_commit();

        const h16* Ah = sA + (kt % STAGES) * STG_ELE;
        const h16* Bh = sB + (kt % STAGES) * STG_ELE;
#pragma unroll
        for (int kk = 0; kk < KTILE; kk += 16) {
            uint32_t a[4][4];
#pragma unroll
            for (int mt = 0; mt < 4; ++mt) {
                int r = wm * 64 + mt * 16 + ln4;
                int c = kk + l4 * 2;
                a[mt][0] = *(const uint32_t*)(Ah + r * LDS_S + c);
                a[mt][1] = *(const uint32_t*)(Ah + (r + 8) * LDS_S + c);
                a[mt][2] = *(const uint32_t*)(Ah + r * LDS_S + c + 8);
                a[mt][3] = *(const uint32_t*)(Ah + (r + 8) * LDS_S + c + 8);
            }
#pragma unroll
            for (int nt = 0; nt < 8; ++nt) {
                int n = wn * 64 + nt * 8 + ln4;
                int c = kk + l4 * 2;
                uint32_t b[2];
                b[0] = *(const uint32_t*)(Bh + n * LDS_S + c);
                b[1] = *(const uint32_t*)(Bh + n * LDS_S + c + 8);
#pragma unroll
                for (int mt = 0; mt < 4; ++mt)
                    mma16816(acc[mt][nt], a[mt], b);
            }
        }
    }

#pragma unroll
    for (int mt = 0; mt < 4; ++mt)
#pragma unroll
        for (int nt = 0; nt < 8; ++nt) {
            int col = colBase + wn * 64 + nt * 8 + l4 * 2;
            if (col >= N) continue;
#pragma unroll
            for (int i = 0; i < 2; ++i) {
                int row = rowBase + wm * 64 + mt * 16 + ln4 + i * 8;
                if (row >= M) continue;
                float v0 = acc[mt][nt][i * 2 + 0] * scale;
                float v1 = acc[mt][nt][i * 2 + 1] * scale;
                if (bias) { v0 += bias[col]; v1 += bias[col + 1]; }
                if (gmode) {
                    float gel = 0.5f * v1 * (1.0f + erff(v1 * 0.7071067811865476f));
                    Ch[cOff + (long long)row * ldc + (col >> 1)] = __float2half(v0 * gel);
                } else {
                    long long o = cOff + (long long)row * ldc + col;
                    if (residual) { v0 += residual[o]; v1 += residual[o + 1]; }
                    if (Cf) { Cf[o] = v0; Cf[o + 1] = v1; }
                    if (Ch) { Ch[o] = __float2half(v0); Ch[o + 1] = __float2half(v1); }
                }
            }
        }
}

// ---------------- fused flash attention (unchanged from R13/R14) ----------------
#define FKSTR 72
#define FVSTR 136
#define FQ_ELE (128 * FKSTR)
#define FK_ELE (128 * FKSTR)
#define FV_ELE (64 * FVSTR)
#define FSMEM_BYTES ((FQ_ELE + 2 * FK_ELE + 2 * FV_ELE) * 2)

__global__ __launch_bounds__(256, 1) void flash_kernel(
    const h16* __restrict__ qh, const h16* __restrict__ kh, const h16* __restrict__ vT,
    h16* __restrict__ att, int Stot, int Sval)
{
    extern __shared__ __align__(16) h16 fsm[];
    h16* sQ = fsm;
    h16* sK = fsm + FQ_ELE;
    h16* sV = fsm + FQ_ELE + 2 * FK_ELE;

    int tid = threadIdx.x;
    int lane = tid & 31, warp = tid >> 5;
    int l4 = lane & 3, ln4 = lane >> 2;
    int bh = blockIdx.y;
    int b = bh / NH, h = bh % NH;
    int qrow0 = blockIdx.x * 128;

    const h16* Qb = qh + (long long)bh * TQ * HD + (long long)qrow0 * HD;
    const h16* Kb = kh + (long long)bh * Stot * HD;
    const h16* Vb = vT + (long long)bh * HD * Stot;

    uint32_t sQ_u = (uint32_t)__cvta_generic_to_shared(sQ);
    uint32_t sK_u = (uint32_t)__cvta_generic_to_shared(sK);
    uint32_t sV_u = (uint32_t)__cvta_generic_to_shared(sV);

    int nk = Stot >> 7;

#pragma unroll
    for (int t = 0; t < 4; ++t) {
        int i = tid + t * 256;
        int r = i >> 3, c = (i & 7) << 3;
        cpasync16(sQ_u + (uint32_t)(r * FKSTR + c) * 2, Qb + r * HD + c, true);
    }
    cp_commit();

    auto issueKV = [&](int st, int kt) {
        uint32_t kb = sK_u + st * (FK_ELE * 2);
        uint32_t vb = sV_u + st * (FV_ELE * 2);
#pragma unroll
        for (int t = 0; t < 4; ++t) {
            int i = tid + t * 256;
            int r = i >> 3, c = (i & 7) << 3;
            cpasync16(kb + (uint32_t)(r * FKSTR + c) * 2, Kb + (long long)(kt * 128 + r) * HD + c, true);
            int vr = i >> 4, vc = (i & 15) << 3;
            cpasync16(vb + (uint32_t)(vr * FVSTR + vc) * 2, Vb + (long long)vr * Stot + kt * 128 + vc, true);
        }
    };
    issueKV(0, 0);
    cp_commit();

    cp_wait1();
    __syncthreads();

    uint32_t qa[4][4];
    {
        const h16* Qw = sQ + (warp * 16) * FKSTR;
#pragma unroll
        for (int kk = 0; kk < 4; ++kk) {
            int c = kk * 16 + l4 * 2;
            qa[kk][0] = *(const uint32_t*)(Qw + ln4 * FKSTR + c);
            qa[kk][1] = *(const uint32_t*)(Qw + (ln4 + 8) * FKSTR + c);
            qa[kk][2] = *(const uint32_t*)(Qw + ln4 * FKSTR + c + 8);
            qa[kk][3] = *(const uint32_t*)(Qw + (ln4 + 8) * FKSTR + c + 8);
        }
    }

    float m0 = -1e30f, m1 = -1e30f, le0 = 0.f, le1 = 0.f;
    float oc[8][4];
#pragma unroll
    for (int n = 0; n < 8; ++n)
#pragma unroll
        for (int c = 0; c < 4; ++c) oc[n][c] = 0.f;

    bool doMask = (Sval < Stot);

    for (int kt = 0; kt < nk; ++kt) {
        if (kt + 1 < nk) { issueKV((kt + 1) & 1, kt + 1); cp_commit(); cp_wait1(); }
        else cp_wait0();
        __syncthreads();

        const h16* Kt = sK + (kt & 1) * FK_ELE;
        const h16* Vt = sV + (kt & 1) * FV_ELE;

        float sc[16][4];
#pragma unroll
        for (int j = 0; j < 16; ++j)
#pragma unroll
            for (int c = 0; c < 4; ++c) sc[j][c] = 0.f;
#pragma unroll
        for (int kk = 0; kk < 4; ++kk) {
#pragma unroll
            for (int j = 0; j < 16; ++j) {
                uint32_t kb2[2];
                const h16* kp = Kt + (j * 8 + ln4) * FKSTR + kk * 16 + l4 * 2;
                kb2[0] = *(const uint32_t*)(kp);
                kb2[1] = *(const uint32_t*)(kp + 8);
                mma16816(sc[j], qa[kk], kb2);
            }
        }

        if (doMask) {
            int base = kt * 128 + l4 * 2;
#pragma unroll
            for (int j = 0; j < 16; ++j) {
                int col = base + j * 8;
                if (col >= Sval)     { sc[j][0] = -1e30f; sc[j][2] = -1e30f; }
                if (col + 1 >= Sval) { sc[j][1] = -1e30f; sc[j][3] = -1e30f; }
            }
        }

        float mr0 = -1e30f, mr1 = -1e30f;
#pragma unroll
        for (int j = 0; j < 16; ++j) {
            mr0 = fmaxf(mr0, fmaxf(sc[j][0], sc[j][1]));
            mr1 = fmaxf(mr1, fmaxf(sc[j][2], sc[j][3]));
        }
        mr0 = fmaxf(mr0, __shfl_xor_sync(0xffffffffu, mr0, 1));
        mr0 = fmaxf(mr0, __shfl_xor_sync(0xffffffffu, mr0, 2));
        mr1 = fmaxf(mr1, __shfl_xor_sync(0xffffffffu, mr1, 1));
        mr1 = fmaxf(mr1, __shfl_xor_sync(0xffffffffu, mr1, 2));
        float mn0 = fmaxf(m0, mr0), mn1 = fmaxf(m1, mr1);
        float a0 = expf(m0 - mn0), a1 = expf(m1 - mn1);
        float s0 = 0.f, s1 = 0.f;
#pragma unroll
        for (int j = 0; j < 16; ++j) {
            sc[j][0] = expf(sc[j][0] - mn0);
            sc[j][1] = expf(sc[j][1] - mn0);
            sc[j][2] = expf(sc[j][2] - mn1);
            sc[j][3] = expf(sc[j][3] - mn1);
            s0 += sc[j][0] + sc[j][1];
            s1 += sc[j][2] + sc[j][3];
        }
        s0 += __shfl_xor_sync(0xffffffffu, s0, 1);
        s0 += __shfl_xor_sync(0xffffffffu, s0, 2);
        s1 += __shfl_xor_sync(0xffffffffu, s1, 1);
        s1 += __shfl_xor_sync(0xffffffffu, s1, 2);
        le0 = a0 * le0 + s0;
        le1 = a1 * le1 + s1;
        m0 = mn0; m1 = mn1;
#pragma unroll
        for (int n = 0; n < 8; ++n) {
            oc[n][0] *= a0; oc[n][1] *= a0;
            oc[n][2] *= a1; oc[n][3] *= a1;
        }

#pragma unroll
        for (int kk = 0; kk < 8; ++kk) {
            int j0 = kk * 2, j1 = kk * 2 + 1;
            uint32_t pa[4];
            pa[0] = pack_h2(sc[j0][0], sc[j0][1]);
            pa[1] = pack_h2(sc[j0][2], sc[j0][3]);
            pa[2] = pack_h2(sc[j1][0], sc[j1][1]);
            pa[3] = pack_h2(sc[j1][2], sc[j1][3]);
#pragma unroll
            for (int n = 0; n < 8; ++n) {
                uint32_t vb2[2];
                const h16* vp = Vt + (n * 8 + ln4) * FVSTR + kk * 16 + l4 * 2;
                vb2[0] = *(const uint32_t*)(vp);
                vb2[1] = *(const uint32_t*)(vp + 8);
                mma16816(oc[n], pa, vb2);
            }
        }
        __syncthreads();
    }

    float il0 = 1.f / le0, il1 = 1.f / le1;
    int r0 = qrow0 + warp * 16 + ln4;
    int r1 = r0 + 8;
    long long o0 = ((long long)(b * TQ) + r0) * HID + h * HD;
    long long o1 = ((long long)(b * TQ) + r1) * HID + h * HD;
#pragma unroll
    for (int n = 0; n < 8; ++n) {
        int d = n * 8 + l4 * 2;
        uint32_t v0 = pack_h2(oc[n][0] * il0, oc[n][1] * il0);
        uint32_t v1 = pack_h2(oc[n][2] * il1, oc[n][3] * il1);
        *(uint32_t*)(att + o0 + d) = v0;
        *(uint32_t*)(att + o1 + d) = v1;
    }
}

// ---------------- host glue ----------------
static void gemm(const h16* A, const h16* W, const float* bias, const float* res,
                 float* Cf, h16* Ch, int M, int N, int K, int Z,
                 long long aS, long long wS, long long cHi, long long cLo, int cDiv,
                 int ldc, float scale, int gmode = 0) {
    dim3 g((N + 127) / 128, (M + 127) / 128, Z);
    gemm_kernel<<<g, 128, SMEM_BYTES>>>(A, W, bias, res, Cf, Ch, M, N, K, aS, wS, cHi, cLo, cDiv, ldc, scale, gmode);
}

static void f2h(const float* in, h16* out, long long n) {
    f2h_kernel<<<(unsigned)((n + 255) / 256), 256>>>(in, out, n);
}

extern "C" void kernel_launch(void* const* d_in, const int* in_sizes, int n_in,
                              void* d_out, int out_size) {
    const float* x     = (const float*)d_in[0];
    const float* enc   = (const float*)d_in[1];
    const float* ln1g  = (const float*)d_in[2];
    const float* ln1b  = (const float*)d_in[3];
    const float* ln2g  = (const float*)d_in[4];
    const float* ln2b  = (const float*)d_in[5];
    const float* ln3g  = (const float*)d_in[6];
    const float* ln3b  = (const float*)d_in[7];
    const float* wq1   = (const float*)d_in[8];
    const float* wk1   = (const float*)d_in[9];
    const float* wv1   = (const float*)d_in[10];
    const float* wo1   = (const float*)d_in[11];
    const float* bo1   = (const float*)d_in[12];
    const float* wq2   = (const float*)d_in[13];
    const float* wk2   = (const float*)d_in[14];
    const float* wv2   = (const float*)d_in[15];
    const float* wo2   = (const float*)d_in[16];
    const float* bo2   = (const float*)d_in[17];
    const float* wgg   = (const float*)d_in[18];
    const float* bgg   = (const float*)d_in[19];
    const float* wff   = (const float*)d_in[20];
    const float* bff   = (const float*)d_in[21];
    float* out = (float*)d_out;

    static bool attr_done = false;
    if (!attr_done) {
        cudaFuncSetAttribute(gemm_kernel, cudaFuncAttributeMaxDynamicSharedMemorySize, SMEM_BYTES);
        cudaFuncSetAttribute(flash_kernel, cudaFuncAttributeMaxDynamicSharedMemorySize, FSMEM_BYTES);
        attr_done = true;
    }

    h16 *h, *pqkv, *pq, *pkv, *qh, *kh, *vT, *att, *ff, *encb;
    float *xcur, *bggp;
    cudaGetSymbolAddress((void**)&h,     g_h);
    cudaGetSymbolAddress((void**)&pqkv,  g_pqkv);
    cudaGetSymbolAddress((void**)&pq,    g_pq);
    cudaGetSymbolAddress((void**)&pkv,   g_pkv);
    cudaGetSymbolAddress((void**)&qh,    g_qh);
    cudaGetSymbolAddress((void**)&kh,    g_kh);
    cudaGetSymbolAddress((void**)&vT,    g_vT);
    cudaGetSymbolAddress((void**)&att,   g_att);
    cudaGetSymbolAddress((void**)&xcur,  g_x);
    cudaGetSymbolAddress((void**)&ff,    g_ff);
    cudaGetSymbolAddress((void**)&encb,  g_enc);
    cudaGetSymbolAddress((void**)&bggp,  g_bggp);

    h16 *Wqkv1, *Wo1, *Wq2, *Wkv2, *Wo2, *Wgg, *Wff;
    cudaGetSymbolAddress((void**)&Wqkv1, g_wqkv1h);
    cudaGetSymbolAddress((void**)&Wo1,   g_wo1h);
    cudaGetSymbolAddress((void**)&Wq2,   g_wq2h);
    cudaGetSymbolAddress((void**)&Wkv2,  g_wkv2h);
    cudaGetSymbolAddress((void**)&Wo2,   g_wo2h);
    cudaGetSymbolAddress((void**)&Wgg,   g_wggh);
    cudaGetSymbolAddress((void**)&Wff,   g_wffh);

    // weight + encoder conversion (QKV packed, K/V cross packed, geglu permuted)
    f2h(wq1, Wqkv1,                 (long long)HID * HID);
    f2h(wk1, Wqkv1 + HID * HID,     (long long)HID * HID);
    f2h(wv1, Wqkv1 + 2 * HID * HID, (long long)HID * HID);
    f2h(wo1, Wo1, (long long)HID * HID);
    f2h(wq2, Wq2, (long long)HID * HID);
    f2h(wk2, Wkv2,                (long long)HID * CROSSD);
    f2h(wv2, Wkv2 + HID * CROSSD, (long long)HID * CROSSD);
    f2h(wo2, Wo2, (long long)HID * HID);
    {
        long long n = (long long)2 * FFD * HID;
        permute_wgg_kernel<<<(unsigned)((n + 255) / 256), 256>>>(wgg, Wgg);
        permute_bgg_kernel<<<(2 * FFD + 255) / 256, 256>>>(bgg, bggp);
    }
    f2h(wff, Wff, (long long)HID * FFD);
    f2h(enc, encb, (long long)MENC * CROSSD);

    // ---- self attention ----
    ln_kernel<<<M1, 256>>>(x, ln1g, ln1b, h);
    gemm(h, Wqkv1, nullptr, nullptr, nullptr, pqkv, M1, 3 * HID, HID, 1, 0, 0, 0, 0, 1, 3 * HID, 1.f);
    {
        long long nq = (long long)NBH * TQ * HD;
        reshape_q_kernel<<<(unsigned)((nq + 255) / 256), 256>>>(pqkv, qh, 3 * HID, 0);
        reshape_k_kernel<<<(unsigned)((nq + 255) / 256), 256>>>(pqkv, kh, TQ, TQ, 3 * HID, HID);
        reshape_vT_kernel<<<(unsigned)((nq + 255) / 256), 256>>>(pqkv, vT, TQ, TQ, 3 * HID, 2 * HID);
    }
    flash_kernel<<<dim3(TQ / 128, NBH), 256, FSMEM_BYTES>>>(qh, kh, vT, att, TQ, TQ);
    gemm(att, Wo1, bo1, x, xcur, nullptr, M1, HID, HID, 1, 0, 0, 0, 0, 1, HID, 1.f);

    // ---- cross attention ----
    ln_kernel<<<M1, 256>>>(xcur, ln2g, ln2b, h);
    gemm(h, Wq2, nullptr, nullptr, nullptr, pq, M1, HID, HID, 1, 0, 0, 0, 0, 1, HID, 1.f);
    gemm(encb, Wkv2, nullptr, nullptr, nullptr, pkv, MENC, 2 * HID, CROSSD, 1, 0, 0, 0, 0, 1, 2 * HID, 1.f);
    {
        long long nq = (long long)NBH * TQ * HD;
        long long nk = (long long)NBH * SPAD * HD;
        reshape_q_kernel<<<(unsigned)((nq + 255) / 256), 256>>>(pq, qh, HID, 0);
        reshape_k_kernel<<<(unsigned)((nk + 255) / 256), 256>>>(pkv, kh, SENC, SPAD, 2 * HID, 0);
        reshape_vT_kernel<<<(unsigned)((nk + 255) / 256), 256>>>(pkv, vT, SENC, SPAD, 2 * HID, HID);
    }
    flash_kernel<<<dim3(TQ / 128, NBH), 256, FSMEM_BYTES>>>(qh, kh, vT, att, SPAD, SENC);
    gemm(att, Wo2, bo2, xcur, xcur, nullptr, M1, HID, HID, 1, 0, 0, 0, 0, 1, HID, 1.f);

    // ---- GEGLU FF (activation fused into GEMM epilogue) ----
    ln_kernel<<<M1, 256>>>(xcur, ln3g, ln3b, h);
    gemm(h, Wgg, bggp, nullptr, nullptr, ff, M1, 2 * FFD, HID, 1, 0, 0, 0, 0, 1, FFD, 1.f, 1);
    gemm(ff, Wff, bff, xcur, out, nullptr, M1, HID, FFD, 1, 0, 0, 0, 0, 1, HID, 1.f);

    (void)in_sizes; (void)n_in; (void)out_size;
}

// round 16
// speedup vs baseline: 1.2188x; 1.2188x over previous
#include <cuda_runtime.h>
#include <cuda_fp16.h>
#include <cstdint>

#define BATCH 2
#define TQ    2048
#define HID   1280
#define NH    20
#define HD    64
#define CROSSD 2048
#define SENC  77
#define SPAD  128
#define FFD   5120
#define M1    (BATCH*TQ)     /* 4096 */
#define MENC  (BATCH*SENC)   /* 154  */
#define NBH   (BATCH*NH)     /* 40   */

typedef __half h16;

// ---------------- scratch (device globals; no allocation) ----------------
__device__ h16   g_h    [M1*HID];
__device__ h16   g_pqkv [(size_t)M1*3*HID];
__device__ h16   g_pq   [M1*HID];
__device__ h16   g_pkv  [MENC*2*HID];
__device__ h16   g_qh   [(size_t)NBH*TQ*HD];
__device__ h16   g_kh   [(size_t)NBH*TQ*HD];
__device__ h16   g_vT   [(size_t)NBH*HD*TQ];
__device__ h16   g_att  [M1*HID];
__device__ float g_x    [M1*HID];
__device__ h16   g_ff   [(size_t)M1*FFD];
__device__ h16   g_enc  [MENC*CROSSD];
// fp16 weights
__device__ h16   g_wqkv1h[3*HID*HID];
__device__ h16   g_wo1h[HID*HID];
__device__ h16   g_wq2h[HID*HID];
__device__ h16   g_wkv2h[2*HID*CROSSD];
__device__ h16   g_wo2h[HID*HID];
__device__ h16   g_wggh[2*FFD*HID];    // permuted: row 2c = orig c, row 2c+1 = orig FFD+c
__device__ float g_bggp[2*FFD];        // permuted bias
__device__ h16   g_wffh[HID*FFD];

// ---------------- elementwise kernels ----------------
__global__ void f2h_kernel(const float* __restrict__ in, h16* __restrict__ out, long long n) {
    long long i = (long long)blockIdx.x * blockDim.x + threadIdx.x;
    if (i < n) out[i] = __float2half(in[i]);
}

__global__ void permute_wgg_kernel(const float* __restrict__ in, h16* __restrict__ out) {
    long long i = (long long)blockIdx.x * blockDim.x + threadIdx.x;
    if (i >= (long long)2 * FFD * HID) return;
    int k = (int)(i % HID);
    int r = (int)(i / HID);
    int c = r >> 1;
    int srcRow = (r & 1) ? (FFD + c) : c;
    out[i] = __float2half(in[(long long)srcRow * HID + k]);
}

__global__ void permute_bgg_kernel(const float* __restrict__ in, float* __restrict__ out) {
    int i = blockIdx.x * blockDim.x + threadIdx.x;
    if (i >= 2 * FFD) return;
    int c = i >> 1;
    out[i] = in[(i & 1) ? (FFD + c) : c];
}

__global__ void ln_kernel(const float* __restrict__ x, const float* __restrict__ g,
                          const float* __restrict__ b, h16* __restrict__ out) {
    __shared__ float red[256];
    int row = blockIdx.x, tid = threadIdx.x;
    const float* xr = x + (long long)row * HID;
    float v[5], s = 0.f;
#pragma unroll
    for (int i = 0; i < 5; i++) { v[i] = xr[tid + i * 256]; s += v[i]; }
    red[tid] = s; __syncthreads();
    for (int o = 128; o > 0; o >>= 1) { if (tid < o) red[tid] += red[tid + o]; __syncthreads(); }
    float mu = red[0] * (1.0f / HID);
    __syncthreads();
    float sq = 0.f;
#pragma unroll
    for (int i = 0; i < 5; i++) { float d = v[i] - mu; sq += d * d; }
    red[tid] = sq; __syncthreads();
    for (int o = 128; o > 0; o >>= 1) { if (tid < o) red[tid] += red[tid + o]; __syncthreads(); }
    float rs = rsqrtf(red[0] * (1.0f / HID) + 1e-5f);
#pragma unroll
    for (int i = 0; i < 5; i++) {
        int c = tid + i * 256;
        out[(long long)row * HID + c] = __float2half((v[i] - mu) * rs * g[c] + b[c]);
    }
}

__global__ void reshape_q_kernel(const h16* __restrict__ q, h16* __restrict__ qh,
                                 int stride, int colOff) {
    long long idx = (long long)blockIdx.x * blockDim.x + threadIdx.x;
    if (idx >= (long long)NBH * TQ * HD) return;
    int d = idx & (HD - 1);
    long long r = idx >> 6;
    int t = (int)(r % TQ);
    long long bh = r / TQ;
    int h = (int)(bh % NH), b = (int)(bh / NH);
    float v = __half2float(q[((long long)(b * TQ + t)) * stride + colOff + h * HD + d]);
    qh[idx] = __float2half(v * 0.125f);
}

__global__ void reshape_k_kernel(const h16* __restrict__ k, h16* __restrict__ kh,
                                 int S, int Spad, int stride, int colOff) {
    long long idx = (long long)blockIdx.x * blockDim.x + threadIdx.x;
    long long tot = (long long)NBH * Spad * HD;
    if (idx >= tot) return;
    int d = idx & (HD - 1);
    long long r = idx >> 6;
    int s = (int)(r % Spad);
    long long bh = r / Spad;
    int h = (int)(bh % NH), b = (int)(bh / NH);
    h16 val = __float2half(0.f);
    if (s < S) val = k[((long long)(b * S + s)) * stride + colOff + h * HD + d];
    kh[idx] = val;
}

__global__ void reshape_vT_kernel(const h16* __restrict__ v, h16* __restrict__ vT,
                                  int S, int Spad, int stride, int colOff) {
    long long idx = (long long)blockIdx.x * blockDim.x + threadIdx.x;
    long long tot = (long long)NBH * HD * Spad;
    if (idx >= tot) return;
    int s = (int)(idx % Spad);
    long long r = idx / Spad;
    int d = (int)(r % HD);
    long long bh = r / HD;
    int h = (int)(bh % NH), b = (int)(bh / NH);
    h16 val = __float2half(0.f);
    if (s < S) val = v[((long long)(b * S + s)) * stride + colOff + h * HD + d];
    vT[idx] = val;
}

// ---------------- common asm helpers ----------------
__device__ __forceinline__ void mma16816(float c[4], const uint32_t a[4], const uint32_t b[2]) {
    asm volatile(
        "mma.sync.aligned.m16n8k16.row.col.f32.f16.f16.f32 "
        "{%0,%1,%2,%3}, {%4,%5,%6,%7}, {%8,%9}, {%0,%1,%2,%3};\n"
        : "+f"(c[0]), "+f"(c[1]), "+f"(c[2]), "+f"(c[3])
        : "r"(a[0]), "r"(a[1]), "r"(a[2]), "r"(a[3]), "r"(b[0]), "r"(b[1]));
}
__device__ __forceinline__ void cpasync16(uint32_t dst, const void* src, bool pred) {
    int sz = pred ? 16 : 0;
    asm volatile("cp.async.cg.shared.global [%0], [%1], 16, %2;\n"
                 :: "r"(dst), "l"(src), "r"(sz));
}
__device__ __forceinline__ void cp_commit() {
    asm volatile("cp.async.commit_group;\n" ::: "memory");
}
__device__ __forceinline__ void cp_wait0() { asm volatile("cp.async.wait_group 0;\n" ::: "memory"); }
__device__ __forceinline__ void cp_wait1() { asm volatile("cp.async.wait_group 1;\n" ::: "memory"); }
__device__ __forceinline__ uint32_t pack_h2(float a, float b) {
    __half2 v = __floats2half2_rn(a, b);
    return *reinterpret_cast<uint32_t*>(&v);
}

// ---------------- cp.async pipelined batched fp16 GEMM ----------------
// CTA 128x128x64, 128 threads (4 warps 2x2), warp tile 64x64 (128 acc regs):
// 128 B smem fragment traffic per MMA. 2-stage cp.async, smem 90112 B ->
// 2 CTAs/SM resident = 8 warps/SM (fixes R15's 135KB/1-CTA occupancy bug).
// gmode 0: C = scale*(A@W^T)+bias+residual; gmode 1: geglu epilogue.
#define KTILE    64
#define LDS_S    88
#define STG_ELE  (128 * LDS_S)
#define STAGES   2
#define SMEM_BYTES (2 * STAGES * STG_ELE * 2)   /* 90112 */

__global__ __launch_bounds__(128, 2) void gemm_kernel(
    const h16* __restrict__ A, const h16* __restrict__ W,
    const float* __restrict__ bias, const float* __restrict__ residual,
    float* __restrict__ Cf, h16* __restrict__ Ch,
    int M, int N, int K,
    long long aStride, long long wStride,
    long long cHi, long long cLo, int cDiv, int ldc, float scale, int gmode)
{
    extern __shared__ __align__(16) h16 sm[];
    h16* sA = sm;
    h16* sB = sm + STAGES * STG_ELE;

    int z = blockIdx.z;
    A += (long long)z * aStride;
    W += (long long)z * wStride;
    long long cOff = (long long)(z / cDiv) * cHi + (long long)(z % cDiv) * cLo;

    int tid = threadIdx.x;
    int lane = tid & 31, warp = tid >> 5;
    int l4 = lane & 3, ln4 = lane >> 2;
    int wm = warp >> 1, wn = warp & 1;        // 2x2 warp grid, 64x64 warp tile
    int rowBase = blockIdx.y * 128;
    int colBase = blockIdx.x * 128;

    uint32_t sA_u = (uint32_t)__cvta_generic_to_shared(sA);
    uint32_t sB_u = (uint32_t)__cvta_generic_to_shared(sB);

    // copy mapping: 8 chunks of 16B per operand per thread per k-tile
    int cr[8], cc[8];
#pragma unroll
    for (int jt = 0; jt < 8; ++jt) {
        int j = tid + jt * 128;
        cr[jt] = j >> 3;
        cc[jt] = (j & 7) << 3;
    }

    float acc[4][8][4];
#pragma unroll
    for (int i = 0; i < 4; i++)
#pragma unroll
        for (int j = 0; j < 8; j++)
#pragma unroll
            for (int l = 0; l < 4; l++) acc[i][j][l] = 0.f;

    int kTiles = K >> 6;

    auto issue = [&](int st, int k0) {
        uint32_t aBase = sA_u + st * (STG_ELE * 2);
        uint32_t bBase = sB_u + st * (STG_ELE * 2);
#pragma unroll
        for (int jt = 0; jt < 8; ++jt) {
            int r = cr[jt], c = cc[jt];
            uint32_t soff = (uint32_t)(r * LDS_S + c) * 2;
            int gr = rowBase + r;
            int grc = gr < M ? gr : (M - 1);
            cpasync16(aBase + soff, A + (long long)grc * K + k0 + c, gr < M);
            int gn = colBase + r;
            int gnc = gn < N ? gn : (N - 1);
            cpasync16(bBase + soff, W + (long long)gnc * K + k0 + c, gn < N);
        }
    };

    // prologue: 1 stage in flight
    issue(0, 0);
    cp_commit();

    for (int kt = 0; kt < kTiles; ++kt) {
        cp_wait0();
        __syncthreads();
        int nf = kt + 1;
        if (nf < kTiles) issue(nf & 1, nf << 6);
        cp_commit();

        const h16* Ah = sA + (kt & 1) * STG_ELE;
        const h16* Bh = sB + (kt & 1) * STG_ELE;
#pragma unroll
        for (int kk = 0; kk < KTILE; kk += 16) {
            uint32_t a[4][4];
#pragma unroll
            for (int mt = 0; mt < 4; ++mt) {
                int r = wm * 64 + mt * 16 + ln4;
                int c = kk + l4 * 2;
                a[mt][0] = *(const uint32_t*)(Ah + r * LDS_S + c);
                a[mt][1] = *(const uint32_t*)(Ah + (r + 8) * LDS_S + c);
                a[mt][2] = *(const uint32_t*)(Ah + r * LDS_S + c + 8);
                a[mt][3] = *(const uint32_t*)(Ah + (r + 8) * LDS_S + c + 8);
            }
#pragma unroll
            for (int nt = 0; nt < 8; ++nt) {
                int n = wn * 64 + nt * 8 + ln4;
                int c = kk + l4 * 2;
                uint32_t b[2];
                b[0] = *(const uint32_t*)(Bh + n * LDS_S + c);
                b[1] = *(const uint32_t*)(Bh + n * LDS_S + c + 8);
#pragma unroll
                for (int mt = 0; mt < 4; ++mt)
                    mma16816(acc[mt][nt], a[mt], b);
            }
        }
        __syncthreads();
    }

#pragma unroll
    for (int mt = 0; mt < 4; ++mt)
#pragma unroll
        for (int nt = 0; nt < 8; ++nt) {
            int col = colBase + wn * 64 + nt * 8 + l4 * 2;
            if (col >= N) continue;
#pragma unroll
            for (int i = 0; i < 2; ++i) {
                int row = rowBase + wm * 64 + mt * 16 + ln4 + i * 8;
                if (row >= M) continue;
                float v0 = acc[mt][nt][i * 2 + 0] * scale;
                float v1 = acc[mt][nt][i * 2 + 1] * scale;
                if (bias) { v0 += bias[col]; v1 += bias[col + 1]; }
                if (gmode) {
                    float gel = 0.5f * v1 * (1.0f + erff(v1 * 0.7071067811865476f));
                    Ch[cOff + (long long)row * ldc + (col >> 1)] = __float2half(v0 * gel);
                } else {
                    long long o = cOff + (long long)row * ldc + col;
                    if (residual) { v0 += residual[o]; v1 += residual[o + 1]; }
                    if (Cf) { Cf[o] = v0; Cf[o + 1] = v1; }
                    if (Ch) { Ch[o] = __float2half(v0); Ch[o + 1] = __float2half(v1); }
                }
            }
        }
}

// ---------------- fused flash attention (unchanged) ----------------
#define FKSTR 72
#define FVSTR 136
#define FQ_ELE (128 * FKSTR)
#define FK_ELE (128 * FKSTR)
#define FV_ELE (64 * FVSTR)
#define FSMEM_BYTES ((FQ_ELE + 2 * FK_ELE + 2 * FV_ELE) * 2)

__global__ __launch_bounds__(256, 1) void flash_kernel(
    const h16* __restrict__ qh, const h16* __restrict__ kh, const h16* __restrict__ vT,
    h16* __restrict__ att, int Stot, int Sval)
{
    extern __shared__ __align__(16) h16 fsm[];
    h16* sQ = fsm;
    h16* sK = fsm + FQ_ELE;
    h16* sV = fsm + FQ_ELE + 2 * FK_ELE;

    int tid = threadIdx.x;
    int lane = tid & 31, warp = tid >> 5;
    int l4 = lane & 3, ln4 = lane >> 2;
    int bh = blockIdx.y;
    int b = bh / NH, h = bh % NH;
    int qrow0 = blockIdx.x * 128;

    const h16* Qb = qh + (long long)bh * TQ * HD + (long long)qrow0 * HD;
    const h16* Kb = kh + (long long)bh * Stot * HD;
    const h16* Vb = vT + (long long)bh * HD * Stot;

    uint32_t sQ_u = (uint32_t)__cvta_generic_to_shared(sQ);
    uint32_t sK_u = (uint32_t)__cvta_generic_to_shared(sK);
    uint32_t sV_u = (uint32_t)__cvta_generic_to_shared(sV);

    int nk = Stot >> 7;

#pragma unroll
    for (int t = 0; t < 4; ++t) {
        int i = tid + t * 256;
        int r = i >> 3, c = (i & 7) << 3;
        cpasync16(sQ_u + (uint32_t)(r * FKSTR + c) * 2, Qb + r * HD + c, true);
    }
    cp_commit();

    auto issueKV = [&](int st, int kt) {
        uint32_t kb = sK_u + st * (FK_ELE * 2);
        uint32_t vb = sV_u + st * (FV_ELE * 2);
#pragma unroll
        for (int t = 0; t < 4; ++t) {
            int i = tid + t * 256;
            int r = i >> 3, c = (i & 7) << 3;
            cpasync16(kb + (uint32_t)(r * FKSTR + c) * 2, Kb + (long long)(kt * 128 + r) * HD + c, true);
            int vr = i >> 4, vc = (i & 15) << 3;
            cpasync16(vb + (uint32_t)(vr * FVSTR + vc) * 2, Vb + (long long)vr * Stot + kt * 128 + vc, true);
        }
    };
    issueKV(0, 0);
    cp_commit();

    cp_wait1();
    __syncthreads();

    uint32_t qa[4][4];
    {
        const h16* Qw = sQ + (warp * 16) * FKSTR;
#pragma unroll
        for (int kk = 0; kk < 4; ++kk) {
            int c = kk * 16 + l4 * 2;
            qa[kk][0] = *(const uint32_t*)(Qw + ln4 * FKSTR + c);
            qa[kk][1] = *(const uint32_t*)(Qw + (ln4 + 8) * FKSTR + c);
            qa[kk][2] = *(const uint32_t*)(Qw + ln4 * FKSTR + c + 8);
            qa[kk][3] = *(const uint32_t*)(Qw + (ln4 + 8) * FKSTR + c + 8);
        }
    }

    float m0 = -1e30f, m1 = -1e30f, le0 = 0.f, le1 = 0.f;
    float oc[8][4];
#pragma unroll
    for (int n = 0; n < 8; ++n)
#pragma unroll
        for (int c = 0; c < 4; ++c) oc[n][c] = 0.f;

    bool doMask = (Sval < Stot);

    for (int kt = 0; kt < nk; ++kt) {
        if (kt + 1 < nk) { issueKV((kt + 1) & 1, kt + 1); cp_commit(); cp_wait1(); }
        else cp_wait0();
        __syncthreads();

        const h16* Kt = sK + (kt & 1) * FK_ELE;
        const h16* Vt = sV + (kt & 1) * FV_ELE;

        float sc[16][4];
#pragma unroll
        for (int j = 0; j < 16; ++j)
#pragma unroll
            for (int c = 0; c < 4; ++c) sc[j][c] = 0.f;
#pragma unroll
        for (int kk = 0; kk < 4; ++kk) {
#pragma unroll
            for (int j = 0; j < 16; ++j) {
                uint32_t kb2[2];
                const h16* kp = Kt + (j * 8 + ln4) * FKSTR + kk * 16 + l4 * 2;
                kb2[0] = *(const uint32_t*)(kp);
                kb2[1] = *(const uint32_t*)(kp + 8);
                mma16816(sc[j], qa[kk], kb2);
            }
        }

        if (doMask) {
            int base = kt * 128 + l4 * 2;
#pragma unroll
            for (int j = 0; j < 16; ++j) {
                int col = base + j * 8;
                if (col >= Sval)     { sc[j][0] = -1e30f; sc[j][2] = -1e30f; }
                if (col + 1 >= Sval) { sc[j][1] = -1e30f; sc[j][3] = -1e30f; }
            }
        }

        float mr0 = -1e30f, mr1 = -1e30f;
#pragma unroll
        for (int j = 0; j < 16; ++j) {
            mr0 = fmaxf(mr0, fmaxf(sc[j][0], sc[j][1]));
            mr1 = fmaxf(mr1, fmaxf(sc[j][2], sc[j][3]));
        }
        mr0 = fmaxf(mr0, __shfl_xor_sync(0xffffffffu, mr0, 1));
        mr0 = fmaxf(mr0, __shfl_xor_sync(0xffffffffu, mr0, 2));
        mr1 = fmaxf(mr1, __shfl_xor_sync(0xffffffffu, mr1, 1));
        mr1 = fmaxf(mr1, __shfl_xor_sync(0xffffffffu, mr1, 2));
        float mn0 = fmaxf(m0, mr0), mn1 = fmaxf(m1, mr1);
        float a0 = expf(m0 - mn0), a1 = expf(m1 - mn1);
        float s0 = 0.f, s1 = 0.f;
#pragma unroll
        for (int j = 0; j < 16; ++j) {
            sc[j][0] = expf(sc[j][0] - mn0);
            sc[j][1] = expf(sc[j][1] - mn0);
            sc[j][2] = expf(sc[j][2] - mn1);
            sc[j][3] = expf(sc[j][3] - mn1);
            s0 += sc[j][0] + sc[j][1];
            s1 += sc[j][2] + sc[j][3];
        }
        s0 += __shfl_xor_sync(0xffffffffu, s0, 1);
        s0 += __shfl_xor_sync(0xffffffffu, s0, 2);
        s1 += __shfl_xor_sync(0xffffffffu, s1, 1);
        s1 += __shfl_xor_sync(0xffffffffu, s1, 2);
        le0 = a0 * le0 + s0;
        le1 = a1 * le1 + s1;
        m0 = mn0; m1 = mn1;
#pragma unroll
        for (int n = 0; n < 8; ++n) {
            oc[n][0] *= a0; oc[n][1] *= a0;
            oc[n][2] *= a1; oc[n][3] *= a1;
        }

#pragma unroll
        for (int kk = 0; kk < 8; ++kk) {
            int j0 = kk * 2, j1 = kk * 2 + 1;
            uint32_t pa[4];
            pa[0] = pack_h2(sc[j0][0], sc[j0][1]);
            pa[1] = pack_h2(sc[j0][2], sc[j0][3]);
            pa[2] = pack_h2(sc[j1][0], sc[j1][1]);
            pa[3] = pack_h2(sc[j1][2], sc[j1][3]);
#pragma unroll
            for (int n = 0; n < 8; ++n) {
                uint32_t vb2[2];
                const h16* vp = Vt + (n * 8 + ln4) * FVSTR + kk * 16 + l4 * 2;
                vb2[0] = *(const uint32_t*)(vp);
                vb2[1] = *(const uint32_t*)(vp + 8);
                mma16816(oc[n], pa, vb2);
            }
        }
        __syncthreads();
    }

    float il0 = 1.f / le0, il1 = 1.f / le1;
    int r0 = qrow0 + warp * 16 + ln4;
    int r1 = r0 + 8;
    long long o0 = ((long long)(b * TQ) + r0) * HID + h * HD;
    long long o1 = ((long long)(b * TQ) + r1) * HID + h * HD;
#pragma unroll
    for (int n = 0; n < 8; ++n) {
        int d = n * 8 + l4 * 2;
        uint32_t v0 = pack_h2(oc[n][0] * il0, oc[n][1] * il0);
        uint32_t v1 = pack_h2(oc[n][2] * il1, oc[n][3] * il1);
        *(uint32_t*)(att + o0 + d) = v0;
        *(uint32_t*)(att + o1 + d) = v1;
    }
}

// ---------------- host glue ----------------
static void gemm(const h16* A, const h16* W, const float* bias, const float* res,
                 float* Cf, h16* Ch, int M, int N, int K, int Z,
                 long long aS, long long wS, long long cHi, long long cLo, int cDiv,
                 int ldc, float scale, int gmode = 0) {
    dim3 g((N + 127) / 128, (M + 127) / 128, Z);
    gemm_kernel<<<g, 128, SMEM_BYTES>>>(A, W, bias, res, Cf, Ch, M, N, K, aS, wS, cHi, cLo, cDiv, ldc, scale, gmode);
}

static void f2h(const float* in, h16* out, long long n) {
    f2h_kernel<<<(unsigned)((n + 255) / 256), 256>>>(in, out, n);
}

extern "C" void kernel_launch(void* const* d_in, const int* in_sizes, int n_in,
                              void* d_out, int out_size) {
    const float* x     = (const float*)d_in[0];
    const float* enc   = (const float*)d_in[1];
    const float* ln1g  = (const float*)d_in[2];
    const float* ln1b  = (const float*)d_in[3];
    const float* ln2g  = (const float*)d_in[4];
    const float* ln2b  = (const float*)d_in[5];
    const float* ln3g  = (const float*)d_in[6];
    const float* ln3b  = (const float*)d_in[7];
    const float* wq1   = (const float*)d_in[8];
    const float* wk1   = (const float*)d_in[9];
    const float* wv1   = (const float*)d_in[10];
    const float* wo1   = (const float*)d_in[11];
    const float* bo1   = (const float*)d_in[12];
    const float* wq2   = (const float*)d_in[13];
    const float* wk2   = (const float*)d_in[14];
    const float* wv2   = (const float*)d_in[15];
    const float* wo2   = (const float*)d_in[16];
    const float* bo2   = (const float*)d_in[17];
    const float* wgg   = (const float*)d_in[18];
    const float* bgg   = (const float*)d_in[19];
    const float* wff   = (const float*)d_in[20];
    const float* bff   = (const float*)d_in[21];
    float* out = (float*)d_out;

    static bool attr_done = false;
    if (!attr_done) {
        cudaFuncSetAttribute(gemm_kernel, cudaFuncAttributeMaxDynamicSharedMemorySize, SMEM_BYTES);
        cudaFuncSetAttribute(flash_kernel, cudaFuncAttributeMaxDynamicSharedMemorySize, FSMEM_BYTES);
        attr_done = true;
    }

    h16 *h, *pqkv, *pq, *pkv, *qh, *kh, *vT, *att, *ff, *encb;
    float *xcur, *bggp;
    cudaGetSymbolAddress((void**)&h,     g_h);
    cudaGetSymbolAddress((void**)&pqkv,  g_pqkv);
    cudaGetSymbolAddress((void**)&pq,    g_pq);
    cudaGetSymbolAddress((void**)&pkv,   g_pkv);
    cudaGetSymbolAddress((void**)&qh,    g_qh);
    cudaGetSymbolAddress((void**)&kh,    g_kh);
    cudaGetSymbolAddress((void**)&vT,    g_vT);
    cudaGetSymbolAddress((void**)&att,   g_att);
    cudaGetSymbolAddress((void**)&xcur,  g_x);
    cudaGetSymbolAddress((void**)&ff,    g_ff);
    cudaGetSymbolAddress((void**)&encb,  g_enc);
    cudaGetSymbolAddress((void**)&bggp,  g_bggp);

    h16 *Wqkv1, *Wo1, *Wq2, *Wkv2, *Wo2, *Wgg, *Wff;
    cudaGetSymbolAddress((void**)&Wqkv1, g_wqkv1h);
    cudaGetSymbolAddress((void**)&Wo1,   g_wo1h);
    cudaGetSymbolAddress((void**)&Wq2,   g_wq2h);
    cudaGetSymbolAddress((void**)&Wkv2,  g_wkv2h);
    cudaGetSymbolAddress((void**)&Wo2,   g_wo2h);
    cudaGetSymbolAddress((void**)&Wgg,   g_wggh);
    cudaGetSymbolAddress((void**)&Wff,   g_wffh);

    // weight + encoder conversion (QKV packed, K/V cross packed, geglu permuted)
    f2h(wq1, Wqkv1,                 (long long)HID * HID);
    f2h(wk1, Wqkv1 + HID * HID,     (long long)HID * HID);
    f2h(wv1, Wqkv1 + 2 * HID * HID, (long long)HID * HID);
    f2h(wo1, Wo1, (long long)HID * HID);
    f2h(wq2, Wq2, (long long)HID * HID);
    f2h(wk2, Wkv2,                (long long)HID * CROSSD);
    f2h(wv2, Wkv2 + HID * CROSSD, (long long)HID * CROSSD);
    f2h(wo2, Wo2, (long long)HID * HID);
    {
        long long n = (long long)2 * FFD * HID;
        permute_wgg_kernel<<<(unsigned)((n + 255) / 256), 256>>>(wgg, Wgg);
        permute_bgg_kernel<<<(2 * FFD + 255) / 256, 256>>>(bgg, bggp);
    }
    f2h(wff, Wff, (long long)HID * FFD);
    f2h(enc, encb, (long long)MENC * CROSSD);

    // ---- self attention ----
    ln_kernel<<<M1, 256>>>(x, ln1g, ln1b, h);
    gemm(h, Wqkv1, nullptr, nullptr, nullptr, pqkv, M1, 3 * HID, HID, 1, 0, 0, 0, 0, 1, 3 * HID, 1.f);
    {
        long long nq = (long long)NBH * TQ * HD;
        reshape_q_kernel<<<(unsigned)((nq + 255) / 256), 256>>>(pqkv, qh, 3 * HID, 0);
        reshape_k_kernel<<<(unsigned)((nq + 255) / 256), 256>>>(pqkv, kh, TQ, TQ, 3 * HID, HID);
        reshape_vT_kernel<<<(unsigned)((nq + 255) / 256), 256>>>(pqkv, vT, TQ, TQ, 3 * HID, 2 * HID);
    }
    flash_kernel<<<dim3(TQ / 128, NBH), 256, FSMEM_BYTES>>>(qh, kh, vT, att, TQ, TQ);
    gemm(att, Wo1, bo1, x, xcur, nullptr, M1, HID, HID, 1, 0, 0, 0, 0, 1, HID, 1.f);

    // ---- cross attention ----
    ln_kernel<<<M1, 256>>>(xcur, ln2g, ln2b, h);
    gemm(h, Wq2, nullptr, nullptr, nullptr, pq, M1, HID, HID, 1, 0, 0, 0, 0, 1, HID, 1.f);
    gemm(encb, Wkv2, nullptr, nullptr, nullptr, pkv, MENC, 2 * HID, CROSSD, 1, 0, 0, 0, 0, 1, 2 * HID, 1.f);
    {
        long long nq = (long long)NBH * TQ * HD;
        long long nk = (long long)NBH * SPAD * HD;
        reshape_q_kernel<<<(unsigned)((nq + 255) / 256), 256>>>(pq, qh, HID, 0);
        reshape_k_kernel<<<(unsigned)((nk + 255) / 256), 256>>>(pkv, kh, SENC, SPAD, 2 * HID, 0);
        reshape_vT_kernel<<<(unsigned)((nk + 255) / 256), 256>>>(pkv, vT, SENC, SPAD, 2 * HID, HID);
    }
    flash_kernel<<<dim3(TQ / 128, NBH), 256, FSMEM_BYTES>>>(qh, kh, vT, att, SPAD, SENC);
    gemm(att, Wo2, bo2, xcur, xcur, nullptr, M1, HID, HID, 1, 0, 0, 0, 0, 1, HID, 1.f);

    // ---- GEGLU FF (activation fused into GEMM epilogue) ----
    ln_kernel<<<M1, 256>>>(xcur, ln3g, ln3b, h);
    gemm(h, Wgg, bggp, nullptr, nullptr, ff, M1, 2 * FFD, HID, 1, 0, 0, 0, 0, 1, FFD, 1.f, 1);
    gemm(ff, Wff, bff, xcur, out, nullptr, M1, HID, FFD, 1, 0, 0, 0, 0, 1, HID, 1.f);

    (void)in_sizes; (void)n_in; (void)out_size;
}